// round 2
// baseline (speedup 1.0000x reference)
#include <cuda_runtime.h>
#include <math.h>

// Problem constants (fixed by the dataset)
#define N_NODES 50000
#define N_EDGES 800000
#define N_TOT   (N_NODES + N_EDGES)   // edges + self loops = 850000
#define DIN  128
#define DH1  128                       // H*DH
#define DOUT 32
#define NEG_SLOPE 0.2f

// ---------------------------------------------------------------------------
// Scratch (device globals; no runtime allocation allowed)
// ---------------------------------------------------------------------------
__device__ int   g_is64;               // 1 if edge_index buffer is int64
__device__ int   g_deg[N_NODES];
__device__ int   g_rowptr[N_NODES + 1];
__device__ int   g_cursor[N_NODES];
__device__ int   g_col[N_TOT];

__device__ __align__(16) float g_xs1[N_NODES * DH1];   // x @ W1_src + b1_src
__device__ __align__(16) float g_xd1[N_NODES * DH1];   // x @ W1_dst + b1_dst
__device__ __align__(16) float g_h1 [N_NODES * DH1];   // elu(gat1 out + bias1)
__device__ __align__(16) float g_xs2[N_NODES * DOUT];
__device__ __align__(16) float g_xd2[N_NODES * DOUT];

__device__ __forceinline__ float lrelu(float v) {
    return v > 0.f ? v : NEG_SLOPE * v;
}
__device__ __forceinline__ float eluf(float v) {
    return v > 0.f ? v : expm1f(v);
}

// Read edge endpoint e (0..E-1) of row `row` (0=src, 1=dst) handling dtype.
__device__ __forceinline__ int edge_at(const int* __restrict__ ei32,
                                       int row, int e, int is64) {
    if (is64) {
        // int64 little-endian: low word at position 2*(row*E+e)
        return ei32[2 * (row * (long long)N_EDGES + e)];
    } else {
        return ei32[row * N_EDGES + e];
    }
}

// ---------------------------------------------------------------------------
// Dtype detection: sample high words of the first E int64-entries.
// In-bounds under both interpretations (words < 2*E).
// ---------------------------------------------------------------------------
__global__ void k_detect(const int* __restrict__ ei32) {
    __shared__ int nz;
    if (threadIdx.x == 0) nz = 0;
    __syncthreads();
    const int SAMPLES = 4096;
    const int stride = N_EDGES / SAMPLES;   // 195
    for (int k = threadIdx.x; k < SAMPLES; k += blockDim.x) {
        if (ei32[2 * (k * stride) + 1] != 0) nz = 1;
    }
    __syncthreads();
    if (threadIdx.x == 0) g_is64 = (nz == 0) ? 1 : 0;
}

// ---------------------------------------------------------------------------
// CSR construction (by destination node)
// ---------------------------------------------------------------------------
__global__ void k_zero_deg() {
    int i = blockIdx.x * blockDim.x + threadIdx.x;
    if (i < N_NODES) g_deg[i] = 0;
}

__global__ void k_hist(const int* __restrict__ ei32) {
    int e = blockIdx.x * blockDim.x + threadIdx.x;
    if (e >= N_TOT) return;
    int is64 = g_is64;
    int dst = (e < N_EDGES) ? edge_at(ei32, 1, e, is64) : (e - N_EDGES);
    if ((unsigned)dst < (unsigned)N_NODES)
        atomicAdd(&g_deg[dst], 1);
}

// Single-block exclusive scan over 50000 ints (chunked warp-scan)
__global__ void k_scan() {
    __shared__ int ws[32];
    __shared__ int carry;
    int t = threadIdx.x;
    if (t == 0) carry = 0;
    __syncthreads();

    for (int base = 0; base < N_NODES; base += 1024) {
        int i = base + t;
        int v = (i < N_NODES) ? g_deg[i] : 0;
        int x = v;  // inclusive within-warp scan
        #pragma unroll
        for (int d = 1; d < 32; d <<= 1) {
            int y = __shfl_up_sync(0xffffffffu, x, d);
            if ((t & 31) >= d) x += y;
        }
        if ((t & 31) == 31) ws[t >> 5] = x;
        __syncthreads();
        if (t < 32) {
            int y = ws[t];
            #pragma unroll
            for (int d = 1; d < 32; d <<= 1) {
                int z = __shfl_up_sync(0xffffffffu, y, d);
                if (t >= d) y += z;
            }
            ws[t] = y;
        }
        __syncthreads();
        int warp_off = (t >= 32) ? ws[(t >> 5) - 1] : 0;
        int excl = carry + warp_off + x - v;
        if (i < N_NODES) { g_rowptr[i] = excl; g_cursor[i] = excl; }
        int total = ws[31];
        __syncthreads();
        if (t == 0) carry += total;
        __syncthreads();
    }
    if (t == 0) g_rowptr[N_NODES] = carry;
}

__global__ void k_scatter(const int* __restrict__ ei32) {
    int e = blockIdx.x * blockDim.x + threadIdx.x;
    if (e >= N_TOT) return;
    int is64 = g_is64;
    int src, dst;
    if (e < N_EDGES) {
        src = edge_at(ei32, 0, e, is64);
        dst = edge_at(ei32, 1, e, is64);
    } else {
        src = dst = e - N_EDGES;
    }
    if ((unsigned)dst >= (unsigned)N_NODES) return;
    if ((unsigned)src >= (unsigned)N_NODES) src = 0;  // defensive
    int pos = atomicAdd(&g_cursor[dst], 1);
    g_col[pos] = src;
}

// ---------------------------------------------------------------------------
// GEMM 1: x[50000,128] @ {W1_src, W1_dst}[128,128] (+bias), fused: 256 cols.
// Block = 256 threads, 32 rows. x tile in smem (broadcast reads), W in L1.
// ---------------------------------------------------------------------------
__global__ __launch_bounds__(256) void k_gemm1(
    const float* __restrict__ x,
    const float* __restrict__ Wsrc, const float* __restrict__ Wdst,
    const float* __restrict__ bsrc, const float* __restrict__ bdst)
{
    __shared__ float4 sx[32][32];   // 32 rows x 128 floats = 16 KB
    int row0 = blockIdx.x * 32;
    int t = threadIdx.x;

    for (int i = t; i < 32 * 32; i += 256) {
        int r = i >> 5, c = i & 31;
        int row = row0 + r;
        sx[r][c] = (row < N_NODES) ? ((const float4*)x)[row * 32 + c]
                                   : make_float4(0.f, 0.f, 0.f, 0.f);
    }
    __syncthreads();

    int col = t;                         // 0..255
    const float* W = (col < 128) ? Wsrc : Wdst;
    int c = col & 127;

    float acc[32];
    #pragma unroll
    for (int r = 0; r < 32; r++) acc[r] = 0.f;

    for (int kc = 0; kc < 32; kc++) {
        float w0 = W[(4 * kc + 0) * 128 + c];
        float w1 = W[(4 * kc + 1) * 128 + c];
        float w2 = W[(4 * kc + 2) * 128 + c];
        float w3 = W[(4 * kc + 3) * 128 + c];
        #pragma unroll
        for (int r = 0; r < 32; r++) {
            float4 xv = sx[r][kc];
            float a = acc[r];
            a = fmaf(xv.x, w0, a);
            a = fmaf(xv.y, w1, a);
            a = fmaf(xv.z, w2, a);
            a = fmaf(xv.w, w3, a);
            acc[r] = a;
        }
    }

    float b = (col < 128) ? bsrc[c] : bdst[c];
    float* outp = (col < 128) ? g_xs1 : g_xd1;
    #pragma unroll
    for (int r = 0; r < 32; r++) {
        int row = row0 + r;
        if (row < N_NODES) outp[row * 128 + c] = acc[r] + b;
    }
}

// ---------------------------------------------------------------------------
// Edge phase, layer 1: one warp per destination node, online softmax.
// lane l owns elements [4l, 4l+4) -> head l/4. Output fused with bias1 + ELU.
// ---------------------------------------------------------------------------
__global__ __launch_bounds__(256) void k_edge1(
    const float* __restrict__ att, const float* __restrict__ bias)
{
    int g = blockIdx.x * blockDim.x + threadIdx.x;
    int node = g >> 5;
    if (node >= N_NODES) return;
    int lane = g & 31;

    float4 xd = ((const float4*)g_xd1)[node * 32 + lane];
    float4 av = ((const float4*)att)[lane];   // att1 flat [8*16] == element idx

    float m = -1e30f, den = 0.f;
    float4 acc = make_float4(0.f, 0.f, 0.f, 0.f);

    int jend = g_rowptr[node + 1];
    for (int j = g_rowptr[node]; j < jend; ++j) {
        int s = g_col[j];
        float4 msg = ((const float4*)g_xs1)[s * 32 + lane];
        float e0 = lrelu(msg.x + xd.x);
        float e1 = lrelu(msg.y + xd.y);
        float e2 = lrelu(msg.z + xd.z);
        float e3 = lrelu(msg.w + xd.w);
        float p = fmaf(av.x, e0, fmaf(av.y, e1, fmaf(av.z, e2, av.w * e3)));
        p += __shfl_xor_sync(0xffffffffu, p, 1);
        p += __shfl_xor_sync(0xffffffffu, p, 2);   // head logit (4-lane group)

        float mn = fmaxf(m, p);
        float sc = __expf(m - mn);
        float w  = __expf(p - mn);
        den = fmaf(den, sc, w);
        acc.x = fmaf(acc.x, sc, w * msg.x);
        acc.y = fmaf(acc.y, sc, w * msg.y);
        acc.z = fmaf(acc.z, sc, w * msg.z);
        acc.w = fmaf(acc.w, sc, w * msg.w);
        m = mn;
    }

    float inv = 1.0f / den;
    float4 b = ((const float4*)bias)[lane];
    float4 o;
    o.x = eluf(fmaf(acc.x, inv, b.x));
    o.y = eluf(fmaf(acc.y, inv, b.y));
    o.z = eluf(fmaf(acc.z, inv, b.z));
    o.w = eluf(fmaf(acc.w, inv, b.w));
    ((float4*)g_h1)[node * 32 + lane] = o;
}

// ---------------------------------------------------------------------------
// GEMM 2: h1[50000,128] @ {W2_src, W2_dst}[128,32] (+bias), fused: 64 cols.
// Block = 256 threads, 64 rows; col = t&63, row-group = t>>6 (16 rows each).
// ---------------------------------------------------------------------------
__global__ __launch_bounds__(256) void k_gemm2(
    const float* __restrict__ Wsrc, const float* __restrict__ Wdst,
    const float* __restrict__ bsrc, const float* __restrict__ bdst)
{
    __shared__ float4 sx[64][32];   // 64 rows x 128 floats = 32 KB
    int row0 = blockIdx.x * 64;
    int t = threadIdx.x;

    for (int i = t; i < 64 * 32; i += 256) {
        int r = i >> 5, c = i & 31;
        int row = row0 + r;
        sx[r][c] = (row < N_NODES) ? ((const float4*)g_h1)[row * 32 + c]
                                   : make_float4(0.f, 0.f, 0.f, 0.f);
    }
    __syncthreads();

    int col = t & 63;
    int rg  = t >> 6;                    // 0..3 -> rows rg*16 .. rg*16+15
    const float* W = (col < 32) ? Wsrc : Wdst;
    int c = col & 31;

    float acc[16];
    #pragma unroll
    for (int r = 0; r < 16; r++) acc[r] = 0.f;

    for (int kc = 0; kc < 32; kc++) {
        float w0 = W[(4 * kc + 0) * 32 + c];
        float w1 = W[(4 * kc + 1) * 32 + c];
        float w2 = W[(4 * kc + 2) * 32 + c];
        float w3 = W[(4 * kc + 3) * 32 + c];
        #pragma unroll
        for (int r = 0; r < 16; r++) {
            float4 xv = sx[rg * 16 + r][kc];
            float a = acc[r];
            a = fmaf(xv.x, w0, a);
            a = fmaf(xv.y, w1, a);
            a = fmaf(xv.z, w2, a);
            a = fmaf(xv.w, w3, a);
            acc[r] = a;
        }
    }

    float b = (col < 32) ? bsrc[c] : bdst[c];
    float* outp = (col < 32) ? g_xs2 : g_xd2;
    #pragma unroll
    for (int r = 0; r < 16; r++) {
        int row = row0 + rg * 16 + r;
        if (row < N_NODES) outp[row * 32 + c] = acc[r] + b;
    }
}

// ---------------------------------------------------------------------------
// Edge phase, layer 2 (heads=1, DOUT=32): one warp per node, lane = channel.
// Fused with bias2 + log_softmax. Writes final output.
// ---------------------------------------------------------------------------
__global__ __launch_bounds__(256) void k_edge2(
    const float* __restrict__ att, const float* __restrict__ bias,
    float* __restrict__ out)
{
    int g = blockIdx.x * blockDim.x + threadIdx.x;
    int node = g >> 5;
    if (node >= N_NODES) return;
    int lane = g & 31;

    float xd = g_xd2[node * 32 + lane];
    float av = att[lane];

    float m = -1e30f, den = 0.f, acc = 0.f;

    int jend = g_rowptr[node + 1];
    for (int j = g_rowptr[node]; j < jend; ++j) {
        int s = g_col[j];
        float msg = g_xs2[s * 32 + lane];
        float p = av * lrelu(msg + xd);
        #pragma unroll
        for (int d = 1; d < 32; d <<= 1)
            p += __shfl_xor_sync(0xffffffffu, p, d);   // full-warp logit

        float mn = fmaxf(m, p);
        float sc = __expf(m - mn);
        float w  = __expf(p - mn);
        den = fmaf(den, sc, w);
        acc = fmaf(acc, sc, w * msg);
        m = mn;
    }

    float v = acc / den + bias[lane];

    // log_softmax across the 32 lanes
    float mx = v;
    #pragma unroll
    for (int d = 1; d < 32; d <<= 1)
        mx = fmaxf(mx, __shfl_xor_sync(0xffffffffu, mx, d));
    float ex = expf(v - mx);
    float ssum = ex;
    #pragma unroll
    for (int d = 1; d < 32; d <<= 1)
        ssum += __shfl_xor_sync(0xffffffffu, ssum, d);

    out[node * 32 + lane] = v - mx - logf(ssum);
}

// ---------------------------------------------------------------------------
// Launch
// ---------------------------------------------------------------------------
extern "C" void kernel_launch(void* const* d_in, const int* in_sizes, int n_in,
                              void* d_out, int out_size)
{
    const float* x     = (const float*)d_in[0];
    const int*   ei32  = (const int*)d_in[1];   // int32 OR int64 (detected)
    const float* W1s   = (const float*)d_in[2];
    const float* W1d   = (const float*)d_in[3];
    const float* b1s   = (const float*)d_in[4];
    const float* b1d   = (const float*)d_in[5];
    const float* att1  = (const float*)d_in[6];
    const float* bias1 = (const float*)d_in[7];
    const float* W2s   = (const float*)d_in[8];
    const float* W2d   = (const float*)d_in[9];
    const float* b2s   = (const float*)d_in[10];
    const float* b2d   = (const float*)d_in[11];
    const float* att2  = (const float*)d_in[12];
    const float* bias2 = (const float*)d_in[13];
    float* out = (float*)d_out;

    // Dtype detection + CSR build (identical for both layers)
    k_detect<<<1, 256>>>(ei32);
    k_zero_deg<<<(N_NODES + 255) / 256, 256>>>();
    k_hist<<<(N_TOT + 255) / 256, 256>>>(ei32);
    k_scan<<<1, 1024>>>();
    k_scatter<<<(N_TOT + 255) / 256, 256>>>(ei32);

    // Layer 1
    k_gemm1<<<(N_NODES + 31) / 32, 256>>>(x, W1s, W1d, b1s, b1d);
    k_edge1<<<(N_NODES * 32 + 255) / 256, 256>>>(att1, bias1);

    // Layer 2
    k_gemm2<<<(N_NODES + 63) / 64, 256>>>(W2s, W2d, b2s, b2d);
    k_edge2<<<(N_NODES * 32 + 255) / 256, 256>>>(att2, bias2, out);
}

// round 3
// speedup vs baseline: 1.4446x; 1.4446x over previous
#include <cuda_runtime.h>
#include <math.h>

// Problem constants (fixed by the dataset)
#define N_NODES 50000
#define N_EDGES 800000
#define N_TOT   (N_NODES + N_EDGES)   // edges + self loops = 850000
#define DIN  128
#define DH1  128                       // H*DH
#define DOUT 32
#define NEG_SLOPE 0.2f

#define SCAN_CHUNK 1024
#define N_CHUNKS ((N_NODES + SCAN_CHUNK - 1) / SCAN_CHUNK)   // 49

// ---------------------------------------------------------------------------
// Scratch (device globals; no runtime allocation allowed)
// ---------------------------------------------------------------------------
__device__ int   g_is64;               // 1 if edge_index buffer is int64
__device__ int   g_deg[N_NODES];
__device__ int   g_rowptr[N_NODES + 1];
__device__ int   g_cursor[N_NODES];
__device__ int   g_col[N_TOT];
__device__ int   g_blksum[N_CHUNKS];

__device__ __align__(16) float g_xs1[N_NODES * DH1];   // x @ W1_src + b1_src
__device__ __align__(16) float g_xd1[N_NODES * DH1];   // x @ W1_dst + b1_dst
__device__ __align__(16) float g_h1 [N_NODES * DH1];   // elu(gat1 out + bias1)
__device__ __align__(16) float g_xs2[N_NODES * DOUT];
__device__ __align__(16) float g_xd2[N_NODES * DOUT];

__device__ __forceinline__ float lrelu(float v) {
    return v > 0.f ? v : NEG_SLOPE * v;
}
__device__ __forceinline__ float eluf(float v) {
    return v > 0.f ? v : expm1f(v);
}
__device__ __forceinline__ unsigned f2tf32(float f) {
    unsigned u;
    asm("cvt.rna.tf32.f32 %0, %1;" : "=r"(u) : "f"(f));
    return u;
}
__device__ __forceinline__ void mma_tf32(float* c, const unsigned* a, const unsigned* b) {
    asm volatile(
        "mma.sync.aligned.m16n8k8.row.col.f32.tf32.tf32.f32 "
        "{%0,%1,%2,%3}, {%4,%5,%6,%7}, {%8,%9}, {%0,%1,%2,%3};\n"
        : "+f"(c[0]), "+f"(c[1]), "+f"(c[2]), "+f"(c[3])
        : "r"(a[0]), "r"(a[1]), "r"(a[2]), "r"(a[3]), "r"(b[0]), "r"(b[1]));
}

// Read edge endpoint e (0..E-1) of row `row` (0=src, 1=dst) handling dtype.
__device__ __forceinline__ int edge_at(const int* __restrict__ ei32,
                                       int row, int e, int is64) {
    if (is64) {
        return ei32[2 * (row * (long long)N_EDGES + e)];
    } else {
        return ei32[row * N_EDGES + e];
    }
}

// ---------------------------------------------------------------------------
// Init: zero degree counters (all blocks) + dtype detection (block 0).
// ---------------------------------------------------------------------------
__global__ void k_init(const int* __restrict__ ei32) {
    int i = blockIdx.x * blockDim.x + threadIdx.x;
    if (i < N_NODES) g_deg[i] = 0;
    if (blockIdx.x == 0) {
        __shared__ int nz;
        if (threadIdx.x == 0) nz = 0;
        __syncthreads();
        const int SAMPLES = 4096;
        const int stride = N_EDGES / SAMPLES;   // 195
        for (int k = threadIdx.x; k < SAMPLES; k += blockDim.x) {
            if (ei32[2 * (k * stride) + 1] != 0) nz = 1;
        }
        __syncthreads();
        if (threadIdx.x == 0) g_is64 = (nz == 0) ? 1 : 0;
    }
}

// ---------------------------------------------------------------------------
// CSR construction (by destination node)
// ---------------------------------------------------------------------------
__global__ void k_hist(const int* __restrict__ ei32) {
    int e = blockIdx.x * blockDim.x + threadIdx.x;
    if (e >= N_TOT) return;
    int is64 = g_is64;
    int dst = (e < N_EDGES) ? edge_at(ei32, 1, e, is64) : (e - N_EDGES);
    if ((unsigned)dst < (unsigned)N_NODES)
        atomicAdd(&g_deg[dst], 1);
}

// Pass 1: per-chunk exclusive scan (local) + chunk totals.
__global__ __launch_bounds__(SCAN_CHUNK) void k_scan1() {
    __shared__ int ws[32];
    int b = blockIdx.x, t = threadIdx.x;
    int i = b * SCAN_CHUNK + t;
    int v = (i < N_NODES) ? g_deg[i] : 0;
    int x = v;
    #pragma unroll
    for (int d = 1; d < 32; d <<= 1) {
        int y = __shfl_up_sync(0xffffffffu, x, d);
        if ((t & 31) >= d) x += y;
    }
    if ((t & 31) == 31) ws[t >> 5] = x;
    __syncthreads();
    if (t < 32) {
        int y = ws[t];
        #pragma unroll
        for (int d = 1; d < 32; d <<= 1) {
            int z = __shfl_up_sync(0xffffffffu, y, d);
            if (t >= d) y += z;
        }
        ws[t] = y;
    }
    __syncthreads();
    int off = (t >= 32) ? ws[(t >> 5) - 1] : 0;
    int incl = off + x;
    if (i < N_NODES) g_rowptr[i] = incl - v;     // chunk-local exclusive
    if (t == SCAN_CHUNK - 1) g_blksum[b] = incl; // chunk total
}

// Pass 2: exclusive scan of 49 chunk totals (one small block).
__global__ void k_scan2() {
    __shared__ int s[64];
    int t = threadIdx.x;
    int v = (t < N_CHUNKS) ? g_blksum[t] : 0;
    s[t] = v;
    __syncthreads();
    for (int d = 1; d < 64; d <<= 1) {
        int y = (t >= d) ? s[t - d] : 0;
        __syncthreads();
        s[t] += y;
        __syncthreads();
    }
    if (t < N_CHUNKS) g_blksum[t] = s[t] - v;    // exclusive
    if (t == 63) g_rowptr[N_NODES] = s[63];      // grand total
}

// Pass 3: add chunk offsets; init cursors.
__global__ __launch_bounds__(SCAN_CHUNK) void k_scan3() {
    int b = blockIdx.x, t = threadIdx.x;
    int i = b * SCAN_CHUNK + t;
    if (i < N_NODES) {
        int r = g_rowptr[i] + g_blksum[b];
        g_rowptr[i] = r;
        g_cursor[i] = r;
    }
}

__global__ void k_scatter(const int* __restrict__ ei32) {
    int e = blockIdx.x * blockDim.x + threadIdx.x;
    if (e >= N_TOT) return;
    int is64 = g_is64;
    int src, dst;
    if (e < N_EDGES) {
        src = edge_at(ei32, 0, e, is64);
        dst = edge_at(ei32, 1, e, is64);
    } else {
        src = dst = e - N_EDGES;
    }
    if ((unsigned)dst >= (unsigned)N_NODES) return;
    if ((unsigned)src >= (unsigned)N_NODES) src = 0;  // defensive
    int pos = atomicAdd(&g_cursor[dst], 1);
    g_col[pos] = src;
}

// ---------------------------------------------------------------------------
// GEMM 1 (tensor cores, tf32): out[50000,256] = x[50000,128] @ [W1_src|W1_dst]
// Block: 256 thr, tile M=64 x N=256. Warp tile 32x64 (2 m16 x 8 n8, K=16x k8).
// A (x tile) in padded smem; B fragments straight from L1-resident W.
// ---------------------------------------------------------------------------
__global__ __launch_bounds__(256, 2) void k_gemm1(
    const float* __restrict__ x,
    const float* __restrict__ Wsrc, const float* __restrict__ Wdst,
    const float* __restrict__ bsrc, const float* __restrict__ bdst)
{
    __shared__ float sA[64][132];   // padded: bank-conflict-free frag loads
    int r0 = blockIdx.x * 64;
    int t = threadIdx.x;

    // Load x tile 64x128 (zero-pad OOB rows)
    #pragma unroll
    for (int i = 0; i < 8; i++) {
        int idx = t + i * 256;       // float4 index, 0..2047
        int row = idx >> 5;
        int c4  = idx & 31;
        float4 v = make_float4(0.f, 0.f, 0.f, 0.f);
        if (r0 + row < N_NODES) v = ((const float4*)x)[(r0 + row) * 32 + c4];
        *(float4*)&sA[row][c4 * 4] = v;
    }
    __syncthreads();

    int lane   = t & 31;
    int wid    = t >> 5;
    int warp_m = wid & 1;            // 0..1 (32 rows each)
    int warp_n = wid >> 1;           // 0..3 (64 cols each)
    int qid    = lane >> 2;          // 0..7
    int tid4   = lane & 3;           // 0..3

    const float* Wp = (warp_n < 2) ? Wsrc : Wdst;
    int cbase = (warp_n & 1) * 64;

    float acc[2][8][4];
    #pragma unroll
    for (int mt = 0; mt < 2; mt++)
        #pragma unroll
        for (int nt = 0; nt < 8; nt++)
            #pragma unroll
            for (int i = 0; i < 4; i++) acc[mt][nt][i] = 0.f;

    #pragma unroll 4
    for (int ks = 0; ks < 16; ks++) {
        int k0 = ks * 8;
        unsigned a[2][4];
        #pragma unroll
        for (int mt = 0; mt < 2; mt++) {
            int rb = warp_m * 32 + mt * 16;
            a[mt][0] = f2tf32(sA[rb + qid    ][k0 + tid4    ]);
            a[mt][1] = f2tf32(sA[rb + qid + 8][k0 + tid4    ]);
            a[mt][2] = f2tf32(sA[rb + qid    ][k0 + tid4 + 4]);
            a[mt][3] = f2tf32(sA[rb + qid + 8][k0 + tid4 + 4]);
        }
        unsigned b[8][2];
        #pragma unroll
        for (int nt = 0; nt < 8; nt++) {
            int cc = cbase + nt * 8 + qid;
            b[nt][0] = f2tf32(__ldg(&Wp[(k0 + tid4    ) * 128 + cc]));
            b[nt][1] = f2tf32(__ldg(&Wp[(k0 + tid4 + 4) * 128 + cc]));
        }
        #pragma unroll
        for (int mt = 0; mt < 2; mt++)
            #pragma unroll
            for (int nt = 0; nt < 8; nt++)
                mma_tf32(acc[mt][nt], a[mt], b[nt]);
    }

    float* outp = (warp_n < 2) ? g_xs1 : g_xd1;
    const float* bp = (warp_n < 2) ? bsrc : bdst;
    #pragma unroll
    for (int mt = 0; mt < 2; mt++) {
        int row = r0 + warp_m * 32 + mt * 16 + qid;
        #pragma unroll
        for (int nt = 0; nt < 8; nt++) {
            int cc = cbase + nt * 8 + 2 * tid4;
            float b0v = bp[cc], b1v = bp[cc + 1];
            if (row < N_NODES) {
                float2 v = make_float2(acc[mt][nt][0] + b0v, acc[mt][nt][1] + b1v);
                *(float2*)&outp[row * 128 + cc] = v;
            }
            if (row + 8 < N_NODES) {
                float2 v = make_float2(acc[mt][nt][2] + b0v, acc[mt][nt][3] + b1v);
                *(float2*)&outp[(row + 8) * 128 + cc] = v;
            }
        }
    }
}

// ---------------------------------------------------------------------------
// Edge phase, layer 1: one warp per destination node, online softmax.
// lane l owns elements [4l, 4l+4) -> head l/4. Output fused with bias1 + ELU.
// ---------------------------------------------------------------------------
__global__ __launch_bounds__(256) void k_edge1(
    const float* __restrict__ att, const float* __restrict__ bias)
{
    int g = blockIdx.x * blockDim.x + threadIdx.x;
    int node = g >> 5;
    if (node >= N_NODES) return;
    int lane = g & 31;

    float4 xd = ((const float4*)g_xd1)[node * 32 + lane];
    float4 av = ((const float4*)att)[lane];   // att1 flat [8*16]

    float m = -1e30f, den = 0.f;
    float4 acc = make_float4(0.f, 0.f, 0.f, 0.f);

    int jend = g_rowptr[node + 1];
    for (int j = g_rowptr[node]; j < jend; ++j) {
        int s = g_col[j];
        float4 msg = ((const float4*)g_xs1)[s * 32 + lane];
        float e0 = lrelu(msg.x + xd.x);
        float e1 = lrelu(msg.y + xd.y);
        float e2 = lrelu(msg.z + xd.z);
        float e3 = lrelu(msg.w + xd.w);
        float p = fmaf(av.x, e0, fmaf(av.y, e1, fmaf(av.z, e2, av.w * e3)));
        p += __shfl_xor_sync(0xffffffffu, p, 1);
        p += __shfl_xor_sync(0xffffffffu, p, 2);   // head logit (4-lane group)

        float mn = fmaxf(m, p);
        float sc = __expf(m - mn);
        float w  = __expf(p - mn);
        den = fmaf(den, sc, w);
        acc.x = fmaf(acc.x, sc, w * msg.x);
        acc.y = fmaf(acc.y, sc, w * msg.y);
        acc.z = fmaf(acc.z, sc, w * msg.z);
        acc.w = fmaf(acc.w, sc, w * msg.w);
        m = mn;
    }

    float inv = 1.0f / den;
    float4 b = ((const float4*)bias)[lane];
    float4 o;
    o.x = eluf(fmaf(acc.x, inv, b.x));
    o.y = eluf(fmaf(acc.y, inv, b.y));
    o.z = eluf(fmaf(acc.z, inv, b.z));
    o.w = eluf(fmaf(acc.w, inv, b.w));
    ((float4*)g_h1)[node * 32 + lane] = o;
}

// ---------------------------------------------------------------------------
// GEMM 2: h1[50000,128] @ {W2_src, W2_dst}[128,32] (+bias), fused: 64 cols.
// ---------------------------------------------------------------------------
__global__ __launch_bounds__(256) void k_gemm2(
    const float* __restrict__ Wsrc, const float* __restrict__ Wdst,
    const float* __restrict__ bsrc, const float* __restrict__ bdst)
{
    __shared__ float4 sx[64][32];   // 64 rows x 128 floats = 32 KB
    int row0 = blockIdx.x * 64;
    int t = threadIdx.x;

    for (int i = t; i < 64 * 32; i += 256) {
        int r = i >> 5, c = i & 31;
        int row = row0 + r;
        sx[r][c] = (row < N_NODES) ? ((const float4*)g_h1)[row * 32 + c]
                                   : make_float4(0.f, 0.f, 0.f, 0.f);
    }
    __syncthreads();

    int col = t & 63;
    int rg  = t >> 6;                    // 0..3 -> rows rg*16 .. rg*16+15
    const float* W = (col < 32) ? Wsrc : Wdst;
    int c = col & 31;

    float acc[16];
    #pragma unroll
    for (int r = 0; r < 16; r++) acc[r] = 0.f;

    for (int kc = 0; kc < 32; kc++) {
        float w0 = W[(4 * kc + 0) * 32 + c];
        float w1 = W[(4 * kc + 1) * 32 + c];
        float w2 = W[(4 * kc + 2) * 32 + c];
        float w3 = W[(4 * kc + 3) * 32 + c];
        #pragma unroll
        for (int r = 0; r < 16; r++) {
            float4 xv = sx[rg * 16 + r][kc];
            float a = acc[r];
            a = fmaf(xv.x, w0, a);
            a = fmaf(xv.y, w1, a);
            a = fmaf(xv.z, w2, a);
            a = fmaf(xv.w, w3, a);
            acc[r] = a;
        }
    }

    float b = (col < 32) ? bsrc[c] : bdst[c];
    float* outp = (col < 32) ? g_xs2 : g_xd2;
    #pragma unroll
    for (int r = 0; r < 16; r++) {
        int row = row0 + rg * 16 + r;
        if (row < N_NODES) outp[row * 32 + c] = acc[r] + b;
    }
}

// ---------------------------------------------------------------------------
// Edge phase, layer 2 (heads=1, DOUT=32): one warp per node, lane = channel.
// Fused with bias2 + log_softmax. Writes final output.
// ---------------------------------------------------------------------------
__global__ __launch_bounds__(256) void k_edge2(
    const float* __restrict__ att, const float* __restrict__ bias,
    float* __restrict__ out)
{
    int g = blockIdx.x * blockDim.x + threadIdx.x;
    int node = g >> 5;
    if (node >= N_NODES) return;
    int lane = g & 31;

    float xd = g_xd2[node * 32 + lane];
    float av = att[lane];

    float m = -1e30f, den = 0.f, acc = 0.f;

    int jend = g_rowptr[node + 1];
    for (int j = g_rowptr[node]; j < jend; ++j) {
        int s = g_col[j];
        float msg = g_xs2[s * 32 + lane];
        float p = av * lrelu(msg + xd);
        #pragma unroll
        for (int d = 1; d < 32; d <<= 1)
            p += __shfl_xor_sync(0xffffffffu, p, d);   // full-warp logit

        float mn = fmaxf(m, p);
        float sc = __expf(m - mn);
        float w  = __expf(p - mn);
        den = fmaf(den, sc, w);
        acc = fmaf(acc, sc, w * msg);
        m = mn;
    }

    float v = acc / den + bias[lane];

    // log_softmax across the 32 lanes
    float mx = v;
    #pragma unroll
    for (int d = 1; d < 32; d <<= 1)
        mx = fmaxf(mx, __shfl_xor_sync(0xffffffffu, mx, d));
    float ex = expf(v - mx);
    float ssum = ex;
    #pragma unroll
    for (int d = 1; d < 32; d <<= 1)
        ssum += __shfl_xor_sync(0xffffffffu, ssum, d);

    out[node * 32 + lane] = v - mx - logf(ssum);
}

// ---------------------------------------------------------------------------
// Launch
// ---------------------------------------------------------------------------
extern "C" void kernel_launch(void* const* d_in, const int* in_sizes, int n_in,
                              void* d_out, int out_size)
{
    const float* x     = (const float*)d_in[0];
    const int*   ei32  = (const int*)d_in[1];   // int32 OR int64 (detected)
    const float* W1s   = (const float*)d_in[2];
    const float* W1d   = (const float*)d_in[3];
    const float* b1s   = (const float*)d_in[4];
    const float* b1d   = (const float*)d_in[5];
    const float* att1  = (const float*)d_in[6];
    const float* bias1 = (const float*)d_in[7];
    const float* W2s   = (const float*)d_in[8];
    const float* W2d   = (const float*)d_in[9];
    const float* b2s   = (const float*)d_in[10];
    const float* b2d   = (const float*)d_in[11];
    const float* att2  = (const float*)d_in[12];
    const float* bias2 = (const float*)d_in[13];
    float* out = (float*)d_out;

    // Init + CSR build (identical for both layers)
    k_init<<<(N_NODES + 255) / 256, 256>>>(ei32);
    k_hist<<<(N_TOT + 255) / 256, 256>>>(ei32);
    k_scan1<<<N_CHUNKS, SCAN_CHUNK>>>();
    k_scan2<<<1, 64>>>();
    k_scan3<<<N_CHUNKS, SCAN_CHUNK>>>();
    k_scatter<<<(N_TOT + 255) / 256, 256>>>(ei32);

    // Layer 1
    k_gemm1<<<(N_NODES + 63) / 64, 256>>>(x, W1s, W1d, b1s, b1d);
    k_edge1<<<(N_NODES * 32 + 255) / 256, 256>>>(att1, bias1);

    // Layer 2
    k_gemm2<<<(N_NODES + 63) / 64, 256>>>(W2s, W2d, b2s, b2d);
    k_edge2<<<(N_NODES * 32 + 255) / 256, 256>>>(att2, bias2, out);
}

// round 4
// speedup vs baseline: 1.5565x; 1.0775x over previous
#include <cuda_runtime.h>
#include <math.h>

// Problem constants (fixed by the dataset)
#define N_NODES 50000
#define N_EDGES 800000
#define N_TOT   (N_NODES + N_EDGES)   // edges + self loops = 850000
#define DIN  128
#define DH1  128                       // H*DH
#define DOUT 32
#define NEG_SLOPE 0.2f

#define SCAN_CHUNK 1024
#define N_CHUNKS ((N_NODES + SCAN_CHUNK - 1) / SCAN_CHUNK)   // 49

// ---------------------------------------------------------------------------
// Scratch (device globals; no runtime allocation allowed)
// ---------------------------------------------------------------------------
__device__ int   g_is64;               // 1 if edge_index buffer is int64
__device__ int   g_deg[N_NODES];
__device__ int   g_rowptr[N_NODES + 1];
__device__ int   g_cursor[N_NODES];
__device__ int   g_col[N_TOT];
__device__ int   g_blksum[N_CHUNKS];

__device__ __align__(16) float g_xs1[N_NODES * DH1];   // x @ W1_src + b1_src
__device__ __align__(16) float g_xd1[N_NODES * DH1];   // x @ W1_dst + b1_dst
__device__ __align__(16) float g_h1 [N_NODES * DH1];   // elu(gat1 out + bias1)
__device__ __align__(16) float g_xs2[N_NODES * DOUT];
__device__ __align__(16) float g_xd2[N_NODES * DOUT];

__device__ __forceinline__ float lrelu(float v) {
    return v > 0.f ? v : NEG_SLOPE * v;
}
__device__ __forceinline__ float eluf(float v) {
    return v > 0.f ? v : expm1f(v);
}
__device__ __forceinline__ unsigned f2tf32(float f) {
    unsigned u;
    asm("cvt.rna.tf32.f32 %0, %1;" : "=r"(u) : "f"(f));
    return u;
}
__device__ __forceinline__ void mma_tf32(float* c, const unsigned* a, const unsigned* b) {
    asm volatile(
        "mma.sync.aligned.m16n8k8.row.col.f32.tf32.tf32.f32 "
        "{%0,%1,%2,%3}, {%4,%5,%6,%7}, {%8,%9}, {%0,%1,%2,%3};\n"
        : "+f"(c[0]), "+f"(c[1]), "+f"(c[2]), "+f"(c[3])
        : "r"(a[0]), "r"(a[1]), "r"(a[2]), "r"(a[3]), "r"(b[0]), "r"(b[1]));
}

// Read edge endpoint e (0..E-1) of row `row` (0=src, 1=dst) handling dtype.
__device__ __forceinline__ int edge_at(const int* __restrict__ ei32,
                                       int row, int e, int is64) {
    if (is64) {
        return ((const int2*)ei32)[row * (long long)N_EDGES + e].x;
    } else {
        return ei32[row * N_EDGES + e];
    }
}

// ---------------------------------------------------------------------------
// Init: zero degree counters (all blocks) + dtype detection (block 0).
// ---------------------------------------------------------------------------
__global__ void k_init(const int* __restrict__ ei32) {
    int i = blockIdx.x * blockDim.x + threadIdx.x;
    if (i < N_NODES) g_deg[i] = 0;
    if (blockIdx.x == 0) {
        __shared__ int nz;
        if (threadIdx.x == 0) nz = 0;
        __syncthreads();
        const int SAMPLES = 4096;
        const int stride = N_EDGES / SAMPLES;   // 195
        for (int k = threadIdx.x; k < SAMPLES; k += blockDim.x) {
            if (ei32[2 * (k * stride) + 1] != 0) nz = 1;
        }
        __syncthreads();
        if (threadIdx.x == 0) g_is64 = (nz == 0) ? 1 : 0;
    }
}

// ---------------------------------------------------------------------------
// CSR construction (by destination node)
// ---------------------------------------------------------------------------
__global__ void k_hist(const int* __restrict__ ei32) {
    int e = blockIdx.x * blockDim.x + threadIdx.x;
    if (e >= N_TOT) return;
    int is64 = g_is64;
    int dst = (e < N_EDGES) ? edge_at(ei32, 1, e, is64) : (e - N_EDGES);
    if ((unsigned)dst < (unsigned)N_NODES)
        atomicAdd(&g_deg[dst], 1);
}

// Pass 1: per-chunk exclusive scan (local) + chunk totals.
__global__ __launch_bounds__(SCAN_CHUNK) void k_scan1() {
    __shared__ int ws[32];
    int b = blockIdx.x, t = threadIdx.x;
    int i = b * SCAN_CHUNK + t;
    int v = (i < N_NODES) ? g_deg[i] : 0;
    int x = v;
    #pragma unroll
    for (int d = 1; d < 32; d <<= 1) {
        int y = __shfl_up_sync(0xffffffffu, x, d);
        if ((t & 31) >= d) x += y;
    }
    if ((t & 31) == 31) ws[t >> 5] = x;
    __syncthreads();
    if (t < 32) {
        int y = ws[t];
        #pragma unroll
        for (int d = 1; d < 32; d <<= 1) {
            int z = __shfl_up_sync(0xffffffffu, y, d);
            if (t >= d) y += z;
        }
        ws[t] = y;
    }
    __syncthreads();
    int off = (t >= 32) ? ws[(t >> 5) - 1] : 0;
    int incl = off + x;
    if (i < N_NODES) g_rowptr[i] = incl - v;     // chunk-local exclusive
    if (t == SCAN_CHUNK - 1) g_blksum[b] = incl; // chunk total
}

// Pass 2: exclusive scan of 49 chunk totals (one small block).
__global__ void k_scan2() {
    __shared__ int s[64];
    int t = threadIdx.x;
    int v = (t < N_CHUNKS) ? g_blksum[t] : 0;
    s[t] = v;
    __syncthreads();
    for (int d = 1; d < 64; d <<= 1) {
        int y = (t >= d) ? s[t - d] : 0;
        __syncthreads();
        s[t] += y;
        __syncthreads();
    }
    if (t < N_CHUNKS) g_blksum[t] = s[t] - v;    // exclusive
    if (t == 63) g_rowptr[N_NODES] = s[63];      // grand total
}

// Pass 3: add chunk offsets; init cursors.
__global__ __launch_bounds__(SCAN_CHUNK) void k_scan3() {
    int b = blockIdx.x, t = threadIdx.x;
    int i = b * SCAN_CHUNK + t;
    if (i < N_NODES) {
        int r = g_rowptr[i] + g_blksum[b];
        g_rowptr[i] = r;
        g_cursor[i] = r;
    }
}

__global__ void k_scatter(const int* __restrict__ ei32) {
    int e = blockIdx.x * blockDim.x + threadIdx.x;
    if (e >= N_TOT) return;
    int is64 = g_is64;
    int src, dst;
    if (e < N_EDGES) {
        src = edge_at(ei32, 0, e, is64);
        dst = edge_at(ei32, 1, e, is64);
    } else {
        src = dst = e - N_EDGES;
    }
    if ((unsigned)dst >= (unsigned)N_NODES) return;
    if ((unsigned)src >= (unsigned)N_NODES) src = 0;  // defensive
    int pos = atomicAdd(&g_cursor[dst], 1);
    g_col[pos] = src;
}

// ---------------------------------------------------------------------------
// GEMM 1 (tensor cores, tf32): out[50000,256] = x[50000,128] @ [W1_src|W1_dst]
// Block: 256 thr, tile M=64 x N=256. Warp tile 32x64 (2 m16 x 8 n8, K=16x k8).
// ---------------------------------------------------------------------------
__global__ __launch_bounds__(256, 2) void k_gemm1(
    const float* __restrict__ x,
    const float* __restrict__ Wsrc, const float* __restrict__ Wdst,
    const float* __restrict__ bsrc, const float* __restrict__ bdst)
{
    __shared__ float sA[64][132];   // padded: bank-conflict-free frag loads
    int r0 = blockIdx.x * 64;
    int t = threadIdx.x;

    #pragma unroll
    for (int i = 0; i < 8; i++) {
        int idx = t + i * 256;       // float4 index, 0..2047
        int row = idx >> 5;
        int c4  = idx & 31;
        float4 v = make_float4(0.f, 0.f, 0.f, 0.f);
        if (r0 + row < N_NODES) v = ((const float4*)x)[(r0 + row) * 32 + c4];
        *(float4*)&sA[row][c4 * 4] = v;
    }
    __syncthreads();

    int lane   = t & 31;
    int wid    = t >> 5;
    int warp_m = wid & 1;            // 0..1 (32 rows each)
    int warp_n = wid >> 1;           // 0..3 (64 cols each)
    int qid    = lane >> 2;          // 0..7
    int tid4   = lane & 3;           // 0..3

    const float* Wp = (warp_n < 2) ? Wsrc : Wdst;
    int cbase = (warp_n & 1) * 64;

    float acc[2][8][4];
    #pragma unroll
    for (int mt = 0; mt < 2; mt++)
        #pragma unroll
        for (int nt = 0; nt < 8; nt++)
            #pragma unroll
            for (int i = 0; i < 4; i++) acc[mt][nt][i] = 0.f;

    #pragma unroll 4
    for (int ks = 0; ks < 16; ks++) {
        int k0 = ks * 8;
        unsigned a[2][4];
        #pragma unroll
        for (int mt = 0; mt < 2; mt++) {
            int rb = warp_m * 32 + mt * 16;
            a[mt][0] = f2tf32(sA[rb + qid    ][k0 + tid4    ]);
            a[mt][1] = f2tf32(sA[rb + qid + 8][k0 + tid4    ]);
            a[mt][2] = f2tf32(sA[rb + qid    ][k0 + tid4 + 4]);
            a[mt][3] = f2tf32(sA[rb + qid + 8][k0 + tid4 + 4]);
        }
        unsigned b[8][2];
        #pragma unroll
        for (int nt = 0; nt < 8; nt++) {
            int cc = cbase + nt * 8 + qid;
            b[nt][0] = f2tf32(__ldg(&Wp[(k0 + tid4    ) * 128 + cc]));
            b[nt][1] = f2tf32(__ldg(&Wp[(k0 + tid4 + 4) * 128 + cc]));
        }
        #pragma unroll
        for (int mt = 0; mt < 2; mt++)
            #pragma unroll
            for (int nt = 0; nt < 8; nt++)
                mma_tf32(acc[mt][nt], a[mt], b[nt]);
    }

    float* outp = (warp_n < 2) ? g_xs1 : g_xd1;
    const float* bp = (warp_n < 2) ? bsrc : bdst;
    #pragma unroll
    for (int mt = 0; mt < 2; mt++) {
        int row = r0 + warp_m * 32 + mt * 16 + qid;
        #pragma unroll
        for (int nt = 0; nt < 8; nt++) {
            int cc = cbase + nt * 8 + 2 * tid4;
            float b0v = bp[cc], b1v = bp[cc + 1];
            if (row < N_NODES) {
                float2 v = make_float2(acc[mt][nt][0] + b0v, acc[mt][nt][1] + b1v);
                *(float2*)&outp[row * 128 + cc] = v;
            }
            if (row + 8 < N_NODES) {
                float2 v = make_float2(acc[mt][nt][2] + b0v, acc[mt][nt][3] + b1v);
                *(float2*)&outp[(row + 8) * 128 + cc] = v;
            }
        }
    }
}

// ---------------------------------------------------------------------------
// Edge phase, layer 1: one warp per destination node, chunked online softmax.
// lane l owns elements [4l, 4l+4) -> head l/4. Output fused with bias1 + ELU.
// ---------------------------------------------------------------------------
#define EC1 8
__global__ __launch_bounds__(256) void k_edge1(
    const float* __restrict__ att, const float* __restrict__ bias)
{
    int g = blockIdx.x * blockDim.x + threadIdx.x;
    int node = g >> 5;
    if (node >= N_NODES) return;
    int lane = g & 31;

    float4 xd = ((const float4*)g_xd1)[node * 32 + lane];
    float4 av = ((const float4*)att)[lane];   // att1 flat [8*16]

    float m = -1e30f, den = 0.f;
    float4 acc = make_float4(0.f, 0.f, 0.f, 0.f);

    int j    = g_rowptr[node];
    int jend = g_rowptr[node + 1];

    // Full chunks of EC1 edges: batched loads (MLP=8), pipelined shuffles,
    // single rescale per chunk.
    for (; j + EC1 <= jend; j += EC1) {
        float4 msg[EC1];
        float  p[EC1];
        #pragma unroll
        for (int k = 0; k < EC1; k++) {
            int s = g_col[j + k];
            msg[k] = ((const float4*)g_xs1)[s * 32 + lane];
        }
        #pragma unroll
        for (int k = 0; k < EC1; k++) {
            float e0 = lrelu(msg[k].x + xd.x);
            float e1 = lrelu(msg[k].y + xd.y);
            float e2 = lrelu(msg[k].z + xd.z);
            float e3 = lrelu(msg[k].w + xd.w);
            p[k] = fmaf(av.x, e0, fmaf(av.y, e1, fmaf(av.z, e2, av.w * e3)));
        }
        #pragma unroll
        for (int k = 0; k < EC1; k++)
            p[k] += __shfl_xor_sync(0xffffffffu, p[k], 1);
        #pragma unroll
        for (int k = 0; k < EC1; k++)
            p[k] += __shfl_xor_sync(0xffffffffu, p[k], 2);

        float cm = p[0];
        #pragma unroll
        for (int k = 1; k < EC1; k++) cm = fmaxf(cm, p[k]);
        float mn = fmaxf(m, cm);
        float sc = __expf(m - mn);
        den *= sc;
        acc.x *= sc; acc.y *= sc; acc.z *= sc; acc.w *= sc;
        #pragma unroll
        for (int k = 0; k < EC1; k++) {
            float w = __expf(p[k] - mn);
            den += w;
            acc.x = fmaf(w, msg[k].x, acc.x);
            acc.y = fmaf(w, msg[k].y, acc.y);
            acc.z = fmaf(w, msg[k].z, acc.z);
            acc.w = fmaf(w, msg[k].w, acc.w);
        }
        m = mn;
    }

    // Remainder edges
    for (; j < jend; ++j) {
        int s = g_col[j];
        float4 msg = ((const float4*)g_xs1)[s * 32 + lane];
        float e0 = lrelu(msg.x + xd.x);
        float e1 = lrelu(msg.y + xd.y);
        float e2 = lrelu(msg.z + xd.z);
        float e3 = lrelu(msg.w + xd.w);
        float p = fmaf(av.x, e0, fmaf(av.y, e1, fmaf(av.z, e2, av.w * e3)));
        p += __shfl_xor_sync(0xffffffffu, p, 1);
        p += __shfl_xor_sync(0xffffffffu, p, 2);

        float mn = fmaxf(m, p);
        float sc = __expf(m - mn);
        float w  = __expf(p - mn);
        den = fmaf(den, sc, w);
        acc.x = fmaf(acc.x, sc, w * msg.x);
        acc.y = fmaf(acc.y, sc, w * msg.y);
        acc.z = fmaf(acc.z, sc, w * msg.z);
        acc.w = fmaf(acc.w, sc, w * msg.w);
        m = mn;
    }

    float inv = 1.0f / den;
    float4 b = ((const float4*)bias)[lane];
    float4 o;
    o.x = eluf(fmaf(acc.x, inv, b.x));
    o.y = eluf(fmaf(acc.y, inv, b.y));
    o.z = eluf(fmaf(acc.z, inv, b.z));
    o.w = eluf(fmaf(acc.w, inv, b.w));
    ((float4*)g_h1)[node * 32 + lane] = o;
}

// ---------------------------------------------------------------------------
// GEMM 2 (tensor cores, tf32): out[50000,64] = h1[50000,128] @ [W2_src|W2_dst]
// Block: 256 thr, tile M=64 x N=64. Warp tile 16x32 (1 m16 x 4 n8, K=16x k8).
// ---------------------------------------------------------------------------
__global__ __launch_bounds__(256, 2) void k_gemm2(
    const float* __restrict__ Wsrc, const float* __restrict__ Wdst,
    const float* __restrict__ bsrc, const float* __restrict__ bdst)
{
    __shared__ float sA[64][132];
    int r0 = blockIdx.x * 64;
    int t = threadIdx.x;

    #pragma unroll
    for (int i = 0; i < 8; i++) {
        int idx = t + i * 256;
        int row = idx >> 5;
        int c4  = idx & 31;
        float4 v = make_float4(0.f, 0.f, 0.f, 0.f);
        if (r0 + row < N_NODES) v = ((const float4*)g_h1)[(r0 + row) * 32 + c4];
        *(float4*)&sA[row][c4 * 4] = v;
    }
    __syncthreads();

    int lane   = t & 31;
    int wid    = t >> 5;
    int warp_m = wid & 3;            // 0..3 (16 rows each)
    int warp_n = wid >> 2;           // 0..1 -> Wsrc / Wdst (32 cols each)
    int qid    = lane >> 2;
    int tid4   = lane & 3;

    const float* Wp = warp_n ? Wdst : Wsrc;

    float acc[4][4];
    #pragma unroll
    for (int nt = 0; nt < 4; nt++)
        #pragma unroll
        for (int i = 0; i < 4; i++) acc[nt][i] = 0.f;

    #pragma unroll 4
    for (int ks = 0; ks < 16; ks++) {
        int k0 = ks * 8;
        unsigned a[4];
        int rb = warp_m * 16;
        a[0] = f2tf32(sA[rb + qid    ][k0 + tid4    ]);
        a[1] = f2tf32(sA[rb + qid + 8][k0 + tid4    ]);
        a[2] = f2tf32(sA[rb + qid    ][k0 + tid4 + 4]);
        a[3] = f2tf32(sA[rb + qid + 8][k0 + tid4 + 4]);

        unsigned b[4][2];
        #pragma unroll
        for (int nt = 0; nt < 4; nt++) {
            int cc = nt * 8 + qid;
            b[nt][0] = f2tf32(__ldg(&Wp[(k0 + tid4    ) * 32 + cc]));
            b[nt][1] = f2tf32(__ldg(&Wp[(k0 + tid4 + 4) * 32 + cc]));
        }
        #pragma unroll
        for (int nt = 0; nt < 4; nt++)
            mma_tf32(acc[nt], a, b[nt]);
    }

    float* outp = warp_n ? g_xd2 : g_xs2;
    const float* bp = warp_n ? bdst : bsrc;
    int row = r0 + warp_m * 16 + qid;
    #pragma unroll
    for (int nt = 0; nt < 4; nt++) {
        int cc = nt * 8 + 2 * tid4;
        float b0v = bp[cc], b1v = bp[cc + 1];
        if (row < N_NODES) {
            float2 v = make_float2(acc[nt][0] + b0v, acc[nt][1] + b1v);
            *(float2*)&outp[row * 32 + cc] = v;
        }
        if (row + 8 < N_NODES) {
            float2 v = make_float2(acc[nt][2] + b0v, acc[nt][3] + b1v);
            *(float2*)&outp[(row + 8) * 32 + cc] = v;
        }
    }
}

// ---------------------------------------------------------------------------
// Edge phase, layer 2 (heads=1, DOUT=32): one warp per node, chunked.
// Fused with bias2 + log_softmax. Writes final output.
// ---------------------------------------------------------------------------
#define EC2 8
__global__ __launch_bounds__(256) void k_edge2(
    const float* __restrict__ att, const float* __restrict__ bias,
    float* __restrict__ out)
{
    int g = blockIdx.x * blockDim.x + threadIdx.x;
    int node = g >> 5;
    if (node >= N_NODES) return;
    int lane = g & 31;

    float xd = g_xd2[node * 32 + lane];
    float av = att[lane];

    float m = -1e30f, den = 0.f, acc = 0.f;

    int j    = g_rowptr[node];
    int jend = g_rowptr[node + 1];

    for (; j + EC2 <= jend; j += EC2) {
        float msg[EC2], p[EC2];
        #pragma unroll
        for (int k = 0; k < EC2; k++) {
            int s = g_col[j + k];
            msg[k] = g_xs2[s * 32 + lane];
        }
        #pragma unroll
        for (int k = 0; k < EC2; k++)
            p[k] = av * lrelu(msg[k] + xd);
        #pragma unroll
        for (int d = 1; d < 32; d <<= 1) {
            #pragma unroll
            for (int k = 0; k < EC2; k++)
                p[k] += __shfl_xor_sync(0xffffffffu, p[k], d);
        }
        float cm = p[0];
        #pragma unroll
        for (int k = 1; k < EC2; k++) cm = fmaxf(cm, p[k]);
        float mn = fmaxf(m, cm);
        float sc = __expf(m - mn);
        den *= sc; acc *= sc;
        #pragma unroll
        for (int k = 0; k < EC2; k++) {
            float w = __expf(p[k] - mn);
            den += w;
            acc = fmaf(w, msg[k], acc);
        }
        m = mn;
    }

    for (; j < jend; ++j) {
        int s = g_col[j];
        float msg = g_xs2[s * 32 + lane];
        float p = av * lrelu(msg + xd);
        #pragma unroll
        for (int d = 1; d < 32; d <<= 1)
            p += __shfl_xor_sync(0xffffffffu, p, d);

        float mn = fmaxf(m, p);
        float sc = __expf(m - mn);
        float w  = __expf(p - mn);
        den = fmaf(den, sc, w);
        acc = fmaf(acc, sc, w * msg);
        m = mn;
    }

    float v = acc / den + bias[lane];

    // log_softmax across the 32 lanes
    float mx = v;
    #pragma unroll
    for (int d = 1; d < 32; d <<= 1)
        mx = fmaxf(mx, __shfl_xor_sync(0xffffffffu, mx, d));
    float ex = expf(v - mx);
    float ssum = ex;
    #pragma unroll
    for (int d = 1; d < 32; d <<= 1)
        ssum += __shfl_xor_sync(0xffffffffu, ssum, d);

    out[node * 32 + lane] = v - mx - logf(ssum);
}

// ---------------------------------------------------------------------------
// Launch
// ---------------------------------------------------------------------------
extern "C" void kernel_launch(void* const* d_in, const int* in_sizes, int n_in,
                              void* d_out, int out_size)
{
    const float* x     = (const float*)d_in[0];
    const int*   ei32  = (const int*)d_in[1];   // int32 OR int64 (detected)
    const float* W1s   = (const float*)d_in[2];
    const float* W1d   = (const float*)d_in[3];
    const float* b1s   = (const float*)d_in[4];
    const float* b1d   = (const float*)d_in[5];
    const float* att1  = (const float*)d_in[6];
    const float* bias1 = (const float*)d_in[7];
    const float* W2s   = (const float*)d_in[8];
    const float* W2d   = (const float*)d_in[9];
    const float* b2s   = (const float*)d_in[10];
    const float* b2d   = (const float*)d_in[11];
    const float* att2  = (const float*)d_in[12];
    const float* bias2 = (const float*)d_in[13];
    float* out = (float*)d_out;

    // Init + CSR build (identical for both layers)
    k_init<<<(N_NODES + 255) / 256, 256>>>(ei32);
    k_hist<<<(N_TOT + 255) / 256, 256>>>(ei32);
    k_scan1<<<N_CHUNKS, SCAN_CHUNK>>>();
    k_scan2<<<1, 64>>>();
    k_scan3<<<N_CHUNKS, SCAN_CHUNK>>>();
    k_scatter<<<(N_TOT + 255) / 256, 256>>>(ei32);

    // Layer 1
    k_gemm1<<<(N_NODES + 63) / 64, 256>>>(x, W1s, W1d, b1s, b1d);
    k_edge1<<<(N_NODES * 32 + 255) / 256, 256>>>(att1, bias1);

    // Layer 2
    k_gemm2<<<(N_NODES + 63) / 64, 256>>>(W2s, W2d, b2s, b2d);
    k_edge2<<<(N_NODES * 32 + 255) / 256, 256>>>(att2, bias2, out);
}